// round 15
// baseline (speedup 1.0000x reference)
#include <cuda_runtime.h>
#include <cuda_bf16.h>
#include <stdint.h>
#include <stddef.h>

#define NN 50000
#define EE 600000
#define Hh 128
#define EDdim 16
#define Bb 256
#define Ll 5
#define NBLK 196                    // ceil(NN/256)
#define PGRID 296                   // persistent grid = 148 SM x 2 CTA
#define STRIDE 136                  // padded bf16 row stride in smem
#define BLO_ELEM (128 * STRIDE)     // lo-plane offset in bf16 elems
#define GEMM_SMEM (2 * 128 * STRIDE * 2)   // B hi+lo: 69,632 bytes

// ======================= device scratch =======================
__device__ float g_x[(size_t)NN * Hh];
__device__ float g_h[(size_t)NN * Hh];
__device__ float g_agg[(size_t)NN * Hh];
__device__ int   g_rowptr[NN + 1];
__device__ int   g_cursor[NN];
__device__ int   g_srcA[EE];
__device__ float g_vn[Bb * Hh];
__device__ __nv_bfloat16 g_whi[15 * Hh * Hh];  // [mat][n][k] transposed split
__device__ __nv_bfloat16 g_wlo[15 * Hh * Hh];

// all scratch that must start at 0 each replay — ONE memset
struct ZeroBlk {
    int   deg[NN];
    float counts[Bb];
    float eagg[(size_t)NN * EDdim];
    float pooled[Ll][Bb * Hh];
};
__device__ ZeroBlk g_z;

// ======================= helpers =======================
__device__ __forceinline__ void packsplit(float2 v, uint32_t& h, uint32_t& l) {
    uint32_t hp;
    asm("cvt.rn.bf16x2.f32 %0, %1, %2;" : "=r"(hp) : "f"(v.y), "f"(v.x));
    float h0 = __uint_as_float(hp << 16);
    float h1 = __uint_as_float(hp & 0xffff0000u);
    uint32_t lp;
    asm("cvt.rn.bf16x2.f32 %0, %1, %2;" : "=r"(lp) : "f"(v.y - h1), "f"(v.x - h0));
    h = hp;
    l = lp;
}

__device__ __forceinline__ void mma16816(float* c, uint32_t a0, uint32_t a1, uint32_t a2,
                                         uint32_t a3, uint32_t b0, uint32_t b1) {
    asm volatile(
        "mma.sync.aligned.m16n8k16.row.col.f32.bf16.bf16.f32 "
        "{%0,%1,%2,%3}, {%4,%5,%6,%7}, {%8,%9}, {%0,%1,%2,%3};"
        : "+f"(c[0]), "+f"(c[1]), "+f"(c[2]), "+f"(c[3])
        : "r"(a0), "r"(a1), "r"(a2), "r"(a3), "r"(b0), "r"(b1));
}

#define LDSM4(r0, r1, r2, r3, addr) \
    asm volatile("ldmatrix.sync.aligned.m8n8.x4.shared.b16 {%0,%1,%2,%3}, [%4];" \
                 : "=r"(r0), "=r"(r1), "=r"(r2), "=r"(r3) : "r"(addr))

__device__ __forceinline__ uint32_t smem_to_u32(const void* p) {
    uint32_t a;
    asm("{ .reg .u64 t; cvta.to.shared.u64 t, %1; cvt.u32.u64 %0, t; }" : "=r"(a) : "l"(p));
    return a;
}

// ======================= combined preprocessing =======================
// blocks [0,960): weight split; [960,1088): vn init; [1088,1284): counts;
// [1284,3628): per-edge deg atomic + eagg REDG atomics.
#define CB_W 960
#define CB_VN (CB_W + 128)
#define CB_CNT (CB_VN + 196)
#define CB_EDGE (CB_CNT + 2344)

__global__ void k_combo(const float* __restrict__ nodeW, const float* __restrict__ m1W,
                        const float* __restrict__ m2W, const float* __restrict__ vninit,
                        const int* __restrict__ batch, const int* __restrict__ dst,
                        const float* __restrict__ eattr) {
    int b = blockIdx.x;
    int t = threadIdx.x;
    if (b < CB_W) {
        int mat = b >> 6;
        int idx = ((b & 63) << 8) + t;
        const float* Wsrc = (mat < 5) ? (nodeW + (size_t)mat * Hh * Hh)
                          : (mat < 10) ? (m1W + (size_t)(mat - 5) * Hh * Hh)
                          : (m2W + (size_t)(mat - 10) * Hh * Hh);
        int n = idx >> 7, k = idx & 127;
        float w = Wsrc[k * Hh + n];
        __nv_bfloat16 hi = __float2bfloat16(w);
        __nv_bfloat16 lo = __float2bfloat16(w - __bfloat162float(hi));
        g_whi[(size_t)mat * Hh * Hh + idx] = hi;
        g_wlo[(size_t)mat * Hh * Hh + idx] = lo;
    } else if (b < CB_VN) {
        int i = (b - CB_W) * 256 + t;       // 0..32767
        g_vn[i] = vninit[i & (Hh - 1)];
    } else if (b < CB_CNT) {
        int i = (b - CB_VN) * 256 + t;
        if (i < NN) atomicAdd(&g_z.counts[batch[i]], 1.0f);
    } else {
        int e = (b - CB_CNT) * 256 + t;
        if (e < EE) {
            int d = dst[e];
            atomicAdd(&g_z.deg[d], 1);
            const float4* ep = (const float4*)(eattr + (size_t)e * EDdim);
            float4 a0 = ep[0], a1 = ep[1], a2 = ep[2], a3 = ep[3];
            float* ea = g_z.eagg + (size_t)d * EDdim;
            atomicAdd(ea + 0, a0.x);  atomicAdd(ea + 1, a0.y);
            atomicAdd(ea + 2, a0.z);  atomicAdd(ea + 3, a0.w);
            atomicAdd(ea + 4, a1.x);  atomicAdd(ea + 5, a1.y);
            atomicAdd(ea + 6, a1.z);  atomicAdd(ea + 7, a1.w);
            atomicAdd(ea + 8, a2.x);  atomicAdd(ea + 9, a2.y);
            atomicAdd(ea + 10, a2.z); atomicAdd(ea + 11, a2.w);
            atomicAdd(ea + 12, a3.x); atomicAdd(ea + 13, a3.y);
            atomicAdd(ea + 14, a3.z); atomicAdd(ea + 15, a3.w);
        }
    }
}

// merged scan: each block computes its global prefix itself, then local scan
__global__ void k_scanfill() {
    __shared__ int s[256];
    __shared__ int sbase;
    int t = threadIdx.x;
    int lim = blockIdx.x * 256;
    int p = 0;
    for (int i = t; i < lim; i += 256) p += g_z.deg[i];
    s[t] = p;
    __syncthreads();
    for (int o = 128; o > 0; o >>= 1) {
        if (t < o) s[t] += s[t + o];
        __syncthreads();
    }
    if (t == 0) sbase = s[0];
    __syncthreads();
    int i = lim + t;
    int v = (i < NN) ? g_z.deg[i] : 0;
    s[t] = v;
    __syncthreads();
    for (int o = 1; o < 256; o <<= 1) {
        int u = (t >= o) ? s[t - o] : 0;
        __syncthreads();
        s[t] += u;
        __syncthreads();
    }
    if (i < NN) {
        int pos = sbase + s[t] - v;
        g_rowptr[i] = pos;
        g_cursor[i] = pos;
    }
    if (blockIdx.x == NBLK - 1 && t == 255) g_rowptr[NN] = sbase + s[255];
}

__global__ void k_fill(const int* __restrict__ src, const int* __restrict__ dst) {
    int e = blockIdx.x * 256 + threadIdx.x;
    if (e >= EE) return;
    int pos = atomicAdd(&g_cursor[dst[e]], 1);
    g_srcA[pos] = src[e];
}

// ======================= persistent HMMA bf16-split GEMM =======================
template <int EPI>
__launch_bounds__(256, 2)
__global__ void gemm_tc(const float* __restrict__ A, const __nv_bfloat16* __restrict__ Whi,
                        const __nv_bfloat16* __restrict__ Wlo, const float* __restrict__ bias,
                        float* __restrict__ C, const int* __restrict__ batch,
                        const float* __restrict__ vn, float* __restrict__ pooled, int M) {
    extern __shared__ __nv_bfloat16 sm[];
    const int tid = threadIdx.x;
    const int wid = tid >> 5;
    const int lane = tid & 31;

#pragma unroll
    for (int it = 0; it < 8; it++) {
        int idx = it * 256 + tid;
        int n = idx >> 4;
        int k8 = (idx & 15) << 3;
        uint4 hv = *(const uint4*)(Whi + (size_t)n * Hh + k8);
        uint4 lv = *(const uint4*)(Wlo + (size_t)n * Hh + k8);
        *(uint4*)&sm[n * STRIDE + k8] = hv;
        *(uint4*)&sm[BLO_ELEM + n * STRIDE + k8] = lv;
    }

    const int wr = wid & 3;
    const int wc = wid >> 2;
    const int g = lane >> 2;
    const int tig = lane & 3;

    const int mq = lane >> 3;
    const int tr = lane & 7;
    const uint32_t smem_u32 = smem_to_u32(sm);
    const uint32_t brow_off = (uint32_t)((((mq >> 1) * 8 + tr) * STRIDE + (mq & 1) * 8) * 2);
    const uint32_t colb = (uint32_t)(wc * 64 * STRIDE * 2);

    __syncthreads();

    for (int tile = blockIdx.x; tile < (M + 127) / 128; tile += gridDim.x) {
        const int tb = tile * 128;
        int grow[4];
        bool gv[4];
        const float* Ap[4];
#pragma unroll
        for (int j = 0; j < 4; j++) {
            grow[j] = tb + wr * 32 + j * 8 + g;
            gv[j] = grow[j] < M;
            Ap[j] = A + (size_t)(gv[j] ? grow[j] : 0) * Hh + 2 * tig;
        }

        float c[2][8][4];
#pragma unroll
        for (int m = 0; m < 2; m++)
#pragma unroll
            for (int n = 0; n < 8; n++)
#pragma unroll
                for (int j = 0; j < 4; j++) c[m][n][j] = 0.f;

        float2 pa[4][2];
#pragma unroll
        for (int j = 0; j < 4; j++) {
            pa[j][0] = *(const float2*)(Ap[j]);
            pa[j][1] = *(const float2*)(Ap[j] + 8);
        }

#pragma unroll 1
        for (int k = 0; k < 8; k++) {
            uint32_t ahA[4], alA[4], ahB[4], alB[4];
#pragma unroll
            for (int j = 0; j < 4; j++) {
                packsplit(pa[j][0], ahA[j], alA[j]);
                packsplit(pa[j][1], ahB[j], alB[j]);
            }
            if (k < 7) {
                int off = (k + 1) << 4;
#pragma unroll
                for (int j = 0; j < 4; j++) {
                    pa[j][0] = *(const float2*)(Ap[j] + off);
                    pa[j][1] = *(const float2*)(Ap[j] + off + 8);
                }
            }
            const uint32_t kb = smem_u32 + brow_off + colb + ((uint32_t)k << 5);
#pragma unroll
            for (int n2 = 0; n2 < 4; n2++) {
                uint32_t ha = kb + (uint32_t)(n2 * 16 * STRIDE * 2);
                uint32_t la = ha + BLO_ELEM * 2;
                uint32_t bh0, bh1, bh2, bh3, bl0, bl1, bl2, bl3;
                LDSM4(bh0, bh1, bh2, bh3, ha);
                LDSM4(bl0, bl1, bl2, bl3, la);
#pragma unroll
                for (int m = 0; m < 2; m++) {
                    uint32_t a0 = ahA[2 * m], a1 = ahA[2 * m + 1];
                    uint32_t a2 = ahB[2 * m], a3 = ahB[2 * m + 1];
                    uint32_t q0 = alA[2 * m], q1 = alA[2 * m + 1];
                    uint32_t q2 = alB[2 * m], q3 = alB[2 * m + 1];
                    mma16816(c[m][2 * n2], a0, a1, a2, a3, bh0, bh1);
                    mma16816(c[m][2 * n2], a0, a1, a2, a3, bl0, bl1);
                    mma16816(c[m][2 * n2], q0, q1, q2, q3, bh0, bh1);
                    mma16816(c[m][2 * n2 + 1], a0, a1, a2, a3, bh2, bh3);
                    mma16816(c[m][2 * n2 + 1], a0, a1, a2, a3, bl2, bl3);
                    mma16816(c[m][2 * n2 + 1], q0, q1, q2, q3, bh2, bh3);
                }
            }
        }

        int gc[4] = {0, 0, 0, 0};
        if (EPI == 0 || EPI == 2) {
#pragma unroll
            for (int j = 0; j < 4; j++)
                if (gv[j]) gc[j] = batch[grow[j]];
        }
#pragma unroll
        for (int m = 0; m < 2; m++) {
            int j0 = 2 * m, j1 = 2 * m + 1;
#pragma unroll
            for (int n = 0; n < 8; n++) {
                int col = wc * 64 + (n << 3) + 2 * tig;
                float2 bv = *(const float2*)(bias + col);
                float o0x = c[m][n][0] + bv.x, o0y = c[m][n][1] + bv.y;
                float o1x = c[m][n][2] + bv.x, o1y = c[m][n][3] + bv.y;
                if (EPI == 0) {
                    if (gv[j0]) {
                        float2 vv = *(const float2*)(vn + gc[j0] * Hh + col);
                        o0x += vv.x; o0y += vv.y;
                    }
                    if (gv[j1]) {
                        float2 vv = *(const float2*)(vn + gc[j1] * Hh + col);
                        o1x += vv.x; o1y += vv.y;
                    }
                } else {
                    o0x = fmaxf(o0x, 0.f); o0y = fmaxf(o0y, 0.f);
                    o1x = fmaxf(o1x, 0.f); o1y = fmaxf(o1y, 0.f);
                }
                if (gv[j0]) {
                    *(float2*)(C + (size_t)grow[j0] * Hh + col) = make_float2(o0x, o0y);
                    if (EPI == 2) {
                        atomicAdd(&pooled[gc[j0] * Hh + col], o0x);
                        atomicAdd(&pooled[gc[j0] * Hh + col + 1], o0y);
                    }
                }
                if (gv[j1]) {
                    *(float2*)(C + (size_t)grow[j1] * Hh + col) = make_float2(o1x, o1y);
                    if (EPI == 2) {
                        atomicAdd(&pooled[gc[j1] * Hh + col], o1x);
                        atomicAdd(&pooled[gc[j1] * Hh + col + 1], o1y);
                    }
                }
            }
        }
    }
}

// ======================= SpMM (unroll-4 edge loop) =======================
__launch_bounds__(256)
__global__ void spmm(const float* __restrict__ h, const float* __restrict__ eW,
                     const float* __restrict__ eb, float* __restrict__ agg) {
    __shared__ float sW[EDdim * Hh];
    for (int i = threadIdx.x; i < EDdim * Hh; i += 256) sW[i] = eW[i];
    __syncthreads();
    int warp = (blockIdx.x * 256 + threadIdx.x) >> 5;
    int lane = threadIdx.x & 31;
    if (warp >= NN) return;
    const int row = warp;
    const int c4 = lane << 2;

    float4 acc = make_float4(0.f, 0.f, 0.f, 0.f);
    const float* ea = g_z.eagg + (size_t)row * EDdim;
#pragma unroll
    for (int k = 0; k < EDdim; k++) {
        float v = ea[k];
        float4 w = *(const float4*)&sW[k * Hh + c4];
        acc.x = fmaf(v, w.x, acc.x);
        acc.y = fmaf(v, w.y, acc.y);
        acc.z = fmaf(v, w.z, acc.z);
        acc.w = fmaf(v, w.w, acc.w);
    }
    int beg = g_rowptr[row];
    int end = g_rowptr[row + 1];
    float degf = (float)(end - beg);
    float4 bb = *(const float4*)(eb + c4);
    acc.x = fmaf(degf, bb.x, acc.x);
    acc.y = fmaf(degf, bb.y, acc.y);
    acc.z = fmaf(degf, bb.z, acc.z);
    acc.w = fmaf(degf, bb.w, acc.w);

    int e = beg;
    for (; e + 3 < end; e += 4) {
        int s0 = g_srcA[e];
        int s1 = g_srcA[e + 1];
        int s2 = g_srcA[e + 2];
        int s3 = g_srcA[e + 3];
        float4 h0 = *(const float4*)(h + (size_t)s0 * Hh + c4);
        float4 h1 = *(const float4*)(h + (size_t)s1 * Hh + c4);
        float4 h2 = *(const float4*)(h + (size_t)s2 * Hh + c4);
        float4 h3 = *(const float4*)(h + (size_t)s3 * Hh + c4);
        acc.x += (h0.x + h1.x) + (h2.x + h3.x);
        acc.y += (h0.y + h1.y) + (h2.y + h3.y);
        acc.z += (h0.z + h1.z) + (h2.z + h3.z);
        acc.w += (h0.w + h1.w) + (h2.w + h3.w);
    }
    for (; e < end; e++) {
        int s0 = g_srcA[e];
        float4 h0 = *(const float4*)(h + (size_t)s0 * Hh + c4);
        acc.x += h0.x;
        acc.y += h0.y;
        acc.z += h0.z;
        acc.w += h0.w;
    }
    *(float4*)(agg + (size_t)row * Hh + c4) = acc;
}

// ======================= small dense tails =======================
__global__ void vn_update(const float* __restrict__ w0, const float* __restrict__ b0,
                          const float* __restrict__ w1, const float* __restrict__ b1,
                          const float* __restrict__ pooled) {
    __shared__ float p[Hh];
    __shared__ float r0[Hh];
    int g = blockIdx.x, j = threadIdx.x;
    float cnt = fmaxf(g_z.counts[g], 1.f);
    p[j] = pooled[g * Hh + j] / cnt;
    __syncthreads();
    float s = b0[j];
    for (int k = 0; k < Hh; k++) s = fmaf(p[k], w0[k * Hh + j], s);
    r0[j] = fmaxf(s, 0.f);
    __syncthreads();
    float s2 = b1[j];
    for (int k = 0; k < Hh; k++) s2 = fmaf(r0[k], w1[k * Hh + j], s2);
    g_vn[g * Hh + j] += fmaxf(s2, 0.f);
}

__global__ void final_fc(const float* __restrict__ fcW, const float* __restrict__ fcb,
                         const float* __restrict__ pooled, float* __restrict__ out) {
    __shared__ float p[Hh];
    int g = blockIdx.x, j = threadIdx.x;
    float cnt = fmaxf(g_z.counts[g], 1.f);
    p[j] = pooled[g * Hh + j] / cnt;
    __syncthreads();
    float s = fcb[j];
    for (int k = 0; k < Hh; k++) s = fmaf(p[k], fcW[k * Hh + j], s);
    out[g * Hh + j] = s;
}

// ======================= launch =======================
extern "C" void kernel_launch(void* const* d_in, const int* in_sizes, int n_in,
                              void* d_out, int out_size) {
    const float* x      = (const float*)d_in[0];
    const float* eattr  = (const float*)d_in[1];
    const float* nodeW  = (const float*)d_in[2];
    const float* nodeB  = (const float*)d_in[3];
    const float* edgeW  = (const float*)d_in[4];
    const float* edgeB  = (const float*)d_in[5];
    const float* m1W    = (const float*)d_in[6];
    const float* m1B    = (const float*)d_in[7];
    const float* m2W    = (const float*)d_in[8];
    const float* m2B    = (const float*)d_in[9];
    const float* vnw0   = (const float*)d_in[10];
    const float* vnb0   = (const float*)d_in[11];
    const float* vnw1   = (const float*)d_in[12];
    const float* vnb1   = (const float*)d_in[13];
    const float* fcW    = (const float*)d_in[14];
    const float* fcB    = (const float*)d_in[15];
    const float* vninit = (const float*)d_in[16];
    const int*   eidx   = (const int*)d_in[17];
    const int*   batch  = (const int*)d_in[18];
    const int* srcp = eidx;
    const int* dstp = eidx + EE;
    float* out = (float*)d_out;

    void *p_z, *p_x, *p_h, *p_agg, *p_vn, *p_whi, *p_wlo;
    cudaGetSymbolAddress(&p_z, g_z);
    cudaGetSymbolAddress(&p_x, g_x);
    cudaGetSymbolAddress(&p_h, g_h);
    cudaGetSymbolAddress(&p_agg, g_agg);
    cudaGetSymbolAddress(&p_vn, g_vn);
    cudaGetSymbolAddress(&p_whi, g_whi);
    cudaGetSymbolAddress(&p_wlo, g_wlo);

    cudaFuncSetAttribute(gemm_tc<0>, cudaFuncAttributeMaxDynamicSharedMemorySize, GEMM_SMEM);
    cudaFuncSetAttribute(gemm_tc<1>, cudaFuncAttributeMaxDynamicSharedMemorySize, GEMM_SMEM);
    cudaFuncSetAttribute(gemm_tc<2>, cudaFuncAttributeMaxDynamicSharedMemorySize, GEMM_SMEM);

    const __nv_bfloat16* whi = (const __nv_bfloat16*)p_whi;
    const __nv_bfloat16* wlo = (const __nv_bfloat16*)p_wlo;
    float* pooled0 = (float*)((char*)p_z + offsetof(ZeroBlk, pooled));

    // launches 1..5, spmm at slot 6 for the ncu -s 5 -c 1 window
    cudaMemsetAsync(p_z, 0, sizeof(ZeroBlk));                         // 1
    k_combo<<<CB_EDGE, 256>>>(nodeW, m1W, m2W, vninit, batch, dstp, eattr);  // 2
    gemm_tc<0><<<PGRID, 256, GEMM_SMEM>>>(x, whi, wlo, nodeB,         // 3
                                          (float*)p_h, batch, (const float*)p_vn, nullptr, NN);
    k_scanfill<<<NBLK, 256>>>();                                      // 4
    k_fill<<<(EE + 255) / 256, 256>>>(srcp, dstp);                    // 5

    const int SPB = (NN + 7) / 8;
    spmm<<<SPB, 256>>>((const float*)p_h, edgeW, edgeB, (float*)p_agg);  // 6 <- profiled

    for (int l = 0; l < Ll; l++) {
        float* pooled_l = pooled0 + (size_t)l * Bb * Hh;
        if (l > 0) {
            gemm_tc<0><<<PGRID, 256, GEMM_SMEM>>>((const float*)p_x, whi + (size_t)l * Hh * Hh,
                                                  wlo + (size_t)l * Hh * Hh, nodeB + l * Hh,
                                                  (float*)p_h, batch, (const float*)p_vn, nullptr, NN);
            spmm<<<SPB, 256>>>((const float*)p_h, edgeW + (size_t)l * EDdim * Hh,
                               edgeB + l * Hh, (float*)p_agg);
        }
        gemm_tc<1><<<PGRID, 256, GEMM_SMEM>>>((const float*)p_agg, whi + (size_t)(5 + l) * Hh * Hh,
                                              wlo + (size_t)(5 + l) * Hh * Hh, m1B + l * Hh,
                                              (float*)p_h, nullptr, nullptr, nullptr, NN);
        gemm_tc<2><<<PGRID, 256, GEMM_SMEM>>>((const float*)p_h, whi + (size_t)(10 + l) * Hh * Hh,
                                              wlo + (size_t)(10 + l) * Hh * Hh, m2B + l * Hh,
                                              (float*)p_x, batch, nullptr, pooled_l, NN);
        if (l < Ll - 1) vn_update<<<Bb, Hh>>>(vnw0, vnb0, vnw1, vnb1, pooled_l);
    }
    final_fc<<<Bb, Hh>>>(fcW, fcB, pooled0 + (size_t)(Ll - 1) * Bb * Hh, out);
}